// round 1
// baseline (speedup 1.0000x reference)
#include <cuda_runtime.h>
#include <math_constants.h>

// Problem constants (fixed by the dataset)
#define B_  4
#define S_  1024
#define E_  1024
#define H_  16
#define D_  64
#define M_  (B_ * S_)          // 4096 rows for projection GEMMs

// Scratch: Q/K/V in [B,H,S,D] layout (fp32). 3 x 16MB static device arrays.
__device__ float g_q[B_ * H_ * S_ * D_];
__device__ float g_k[B_ * H_ * S_ * D_];
__device__ float g_v[B_ * H_ * S_ * D_];

// ---------------------------------------------------------------------------
// QKV projection: Y = X @ W + bias, written to [B,H,S,D] layout.
// Block: 64x64 tile, 256 threads, 4x4 per thread, BK=16.
// blockIdx.z selects which of Q/K/V.
// ---------------------------------------------------------------------------
#define GBM 64
#define GBN 64
#define GBK 16

__global__ __launch_bounds__(256)
void qkv_gemm(const float* __restrict__ X,
              const float* __restrict__ Wq, const float* __restrict__ bq,
              const float* __restrict__ Wk, const float* __restrict__ bk,
              const float* __restrict__ Wv, const float* __restrict__ bv)
{
    const int which = blockIdx.z;
    const float* __restrict__ W    = (which == 0) ? Wq : (which == 1) ? Wk : Wv;
    const float* __restrict__ bias = (which == 0) ? bq : (which == 1) ? bk : bv;
    float* __restrict__ out        = (which == 0) ? g_q : (which == 1) ? g_k : g_v;

    __shared__ float As[GBK][GBM + 1];   // As[k][m] (transposed), +1 pad
    __shared__ float Bs[GBK][GBN];       // Bs[k][n]

    const int m0 = blockIdx.y * GBM;
    const int n0 = blockIdx.x * GBN;
    const int tid = threadIdx.x;
    const int tx = tid & 15;
    const int ty = tid >> 4;

    float acc[4][4] = {};

    for (int k0 = 0; k0 < E_; k0 += GBK) {
        // Load A tile: 64 rows x 16 k. One float4 per thread.
        {
            const int row = tid >> 2;
            const int kq  = tid & 3;
            float4 v = *(const float4*)&X[(m0 + row) * E_ + k0 + kq * 4];
            As[kq * 4 + 0][row] = v.x;
            As[kq * 4 + 1][row] = v.y;
            As[kq * 4 + 2][row] = v.z;
            As[kq * 4 + 3][row] = v.w;
        }
        // Load B tile: 16 k x 64 n. One float4 per thread.
        {
            const int kr = tid >> 4;
            const int nq = tid & 15;
            *(float4*)&Bs[kr][nq * 4] =
                *(const float4*)&W[(k0 + kr) * E_ + n0 + nq * 4];
        }
        __syncthreads();

        #pragma unroll
        for (int kk = 0; kk < GBK; kk++) {
            float a[4], b[4];
            #pragma unroll
            for (int i = 0; i < 4; i++) a[i] = As[kk][ty * 4 + i];
            #pragma unroll
            for (int j = 0; j < 4; j++) b[j] = Bs[kk][tx * 4 + j];
            #pragma unroll
            for (int i = 0; i < 4; i++)
                #pragma unroll
                for (int j = 0; j < 4; j++)
                    acc[i][j] += a[i] * b[j];
        }
        __syncthreads();
    }

    // Write to [B,H,S,D] layout. Entire 64-col tile sits inside one head
    // (GBN == D_ and n0 is a multiple of 64), so writes are contiguous float4.
    const int h = n0 >> 6;  // n0 / D_
    float bj[4];
    #pragma unroll
    for (int j = 0; j < 4; j++) bj[j] = bias[n0 + tx * 4 + j];

    #pragma unroll
    for (int i = 0; i < 4; i++) {
        const int m = m0 + ty * 4 + i;
        const int b = m >> 10;        // m / S_
        const int s = m & (S_ - 1);
        float4 o;
        o.x = acc[i][0] + bj[0];
        o.y = acc[i][1] + bj[1];
        o.z = acc[i][2] + bj[2];
        o.w = acc[i][3] + bj[3];
        *(float4*)&out[(((b * H_ + h) << 10) + s) * D_ + tx * 4] = o;
    }
}

// ---------------------------------------------------------------------------
// Flash-style attention. One block = 64 query rows of one (b,h).
// 256 threads, 4x4 scores / 4x4 output per thread. Online softmax with
// width-16 shuffle reductions (lane group == row group by construction).
// Exact mask semantics of the reference (invalid rows -> uniform 1/S).
// ---------------------------------------------------------------------------
#define AT_SMEM_FLOATS (64*64 /*Qs*/ + 64*68 /*Kts*/ + 64*64 /*Vs*/ + 64*64 /*Ps*/)

__global__ __launch_bounds__(256)
void attn_kernel(const int* __restrict__ lens, float* __restrict__ out)
{
    extern __shared__ float smem[];
    float* Qs  = smem;                         // [64][64]
    float* Kts = Qs  + 64 * 64;                // [64][68]  K transposed: Kts[d][c]
    float* Vs  = Kts + 64 * 68;                // [64][64]
    float* Ps  = Vs  + 64 * 64;                // [64][64]

    const int bh = blockIdx.y;
    const int b  = bh >> 4;
    const int h  = bh & (H_ - 1);
    const int len = lens[b];
    const int q0 = blockIdx.x * 64;

    const float* __restrict__ Q = g_q + bh * S_ * D_;
    const float* __restrict__ K = g_k + bh * S_ * D_;
    const float* __restrict__ V = g_v + bh * S_ * D_;

    const int tid = threadIdx.x;
    const int tx = tid & 15;
    const int ty = tid >> 4;

    // Load Q tile (64 x 64): 1024 float4, 4 per thread.
    #pragma unroll
    for (int u = 0; u < 4; u++) {
        const int idx = tid + u * 256;
        const int r = idx >> 4, dq = idx & 15;
        *(float4*)&Qs[r * 64 + dq * 4] = *(const float4*)&Q[(q0 + r) * D_ + dq * 4];
    }

    float m_i[4], l_i[4], o[4][4];
    #pragma unroll
    for (int i = 0; i < 4; i++) {
        m_i[i] = -CUDART_INF_F;
        l_i[i] = 0.f;
        #pragma unroll
        for (int j = 0; j < 4; j++) o[i][j] = 0.f;
    }

    // If every query row in this block is valid, K-tiles fully beyond `len`
    // contribute exactly 0 (exp underflow) — skip them.
    const bool all_valid = (q0 + 64 <= len);
    const int kend = all_valid ? ((len + 63) & ~63) : S_;
    const float scale = 0.125f;  // 1/sqrt(D)

    for (int t0 = 0; t0 < kend; t0 += 64) {
        __syncthreads();  // guard Kts/Vs overwrite vs previous iteration reads

        // Load K (transposed) and V tiles.
        #pragma unroll
        for (int u = 0; u < 4; u++) {
            const int idx = tid + u * 256;
            const int r = idx >> 4, dq = idx & 15;
            float4 kv = *(const float4*)&K[(t0 + r) * D_ + dq * 4];
            Kts[(dq * 4 + 0) * 68 + r] = kv.x;
            Kts[(dq * 4 + 1) * 68 + r] = kv.y;
            Kts[(dq * 4 + 2) * 68 + r] = kv.z;
            Kts[(dq * 4 + 3) * 68 + r] = kv.w;
            *(float4*)&Vs[r * 64 + dq * 4] = *(const float4*)&V[(t0 + r) * D_ + dq * 4];
        }
        __syncthreads();

        // S = Q K^T (64x64 tile, 4x4 per thread)
        float sc[4][4] = {};
        #pragma unroll 16
        for (int d = 0; d < 64; d++) {
            float a[4];
            #pragma unroll
            for (int i = 0; i < 4; i++) a[i] = Qs[(ty * 4 + i) * 64 + d];
            float4 b4 = *(const float4*)&Kts[d * 68 + tx * 4];
            #pragma unroll
            for (int i = 0; i < 4; i++) {
                sc[i][0] += a[i] * b4.x;
                sc[i][1] += a[i] * b4.y;
                sc[i][2] += a[i] * b4.z;
                sc[i][3] += a[i] * b4.w;
            }
        }

        // Mask + scale (reference semantics: invalid -> -1e9 exactly)
        #pragma unroll
        for (int i = 0; i < 4; i++) {
            const bool rv = (q0 + ty * 4 + i) < len;
            #pragma unroll
            for (int j = 0; j < 4; j++) {
                const bool cv = (t0 + tx * 4 + j) < len;
                sc[i][j] = (rv && cv) ? sc[i][j] * scale : -1e9f;
            }
        }

        // Online softmax update
        float alpha[4];
        #pragma unroll
        for (int i = 0; i < 4; i++) {
            float v = fmaxf(fmaxf(sc[i][0], sc[i][1]), fmaxf(sc[i][2], sc[i][3]));
            #pragma unroll
            for (int off = 8; off > 0; off >>= 1)
                v = fmaxf(v, __shfl_xor_sync(0xffffffffu, v, off, 16));
            const float mnew = fmaxf(m_i[i], v);
            alpha[i] = __expf(m_i[i] - mnew);   // exp(-inf)=0 on first tile
            m_i[i] = mnew;

            float s = 0.f;
            #pragma unroll
            for (int j = 0; j < 4; j++) {
                const float p = __expf(sc[i][j] - mnew);
                sc[i][j] = p;
                s += p;
            }
            #pragma unroll
            for (int off = 8; off > 0; off >>= 1)
                s += __shfl_xor_sync(0xffffffffu, s, off, 16);
            l_i[i] = l_i[i] * alpha[i] + s;
            #pragma unroll
            for (int j = 0; j < 4; j++) o[i][j] *= alpha[i];
        }

        // Share P tile
        #pragma unroll
        for (int i = 0; i < 4; i++) {
            float4 p4 = make_float4(sc[i][0], sc[i][1], sc[i][2], sc[i][3]);
            *(float4*)&Ps[(ty * 4 + i) * 64 + tx * 4] = p4;
        }
        __syncthreads();

        // O += P @ V
        #pragma unroll 16
        for (int t = 0; t < 64; t++) {
            float p[4];
            #pragma unroll
            for (int i = 0; i < 4; i++) p[i] = Ps[(ty * 4 + i) * 64 + t];
            float4 v4 = *(const float4*)&Vs[t * 64 + tx * 4];
            #pragma unroll
            for (int i = 0; i < 4; i++) {
                o[i][0] += p[i] * v4.x;
                o[i][1] += p[i] * v4.y;
                o[i][2] += p[i] * v4.z;
                o[i][3] += p[i] * v4.w;
            }
        }
    }

    // Epilogue: normalize and write out [B,S,E] with heads concatenated.
    #pragma unroll
    for (int i = 0; i < 4; i++) {
        const float inv = 1.f / l_i[i];
        const int s = q0 + ty * 4 + i;
        float4 r;
        r.x = o[i][0] * inv;
        r.y = o[i][1] * inv;
        r.z = o[i][2] * inv;
        r.w = o[i][3] * inv;
        *(float4*)&out[(b * S_ + s) * E_ + h * D_ + tx * 4] = r;
    }
}

// ---------------------------------------------------------------------------
extern "C" void kernel_launch(void* const* d_in, const int* in_sizes, int n_in,
                              void* d_out, int out_size)
{
    const float* x   = (const float*)d_in[0];
    const float* Wq  = (const float*)d_in[1];
    const float* bq  = (const float*)d_in[2];
    const float* Wk  = (const float*)d_in[3];
    const float* bk  = (const float*)d_in[4];
    const float* Wv  = (const float*)d_in[5];
    const float* bv  = (const float*)d_in[6];
    const int*  lens = (const int*)d_in[7];
    float* out = (float*)d_out;

    // Projections: grid (N/64, M/64, 3)
    dim3 ggrid(E_ / GBN, M_ / GBM, 3);
    qkv_gemm<<<ggrid, 256>>>(x, Wq, bq, Wk, bk, Wv, bv);

    // Attention: grid (S/64 query tiles, B*H)
    const int smem_bytes = AT_SMEM_FLOATS * (int)sizeof(float);
    cudaFuncSetAttribute(attn_kernel,
                         cudaFuncAttributeMaxDynamicSharedMemorySize, smem_bytes);
    dim3 agrid(S_ / 64, B_ * H_);
    attn_kernel<<<agrid, 256, smem_bytes>>>(lens, out);
}

// round 3
// speedup vs baseline: 1.6270x; 1.6270x over previous
#include <cuda_runtime.h>
#include <cuda_bf16.h>
#include <math_constants.h>
#include <cstdint>

// Problem constants (fixed by the dataset)
#define B_  4
#define S_  1024
#define E_  1024
#define H_  16
#define D_  64
#define M_  (B_ * S_)          // 4096 rows for projection GEMMs

// Scratch: Q/K/V in [B,H,S,D] layout (fp32). 3 x 16MB static device arrays.
__device__ float g_q[B_ * H_ * S_ * D_];
__device__ float g_k[B_ * H_ * S_ * D_];
__device__ float g_v[B_ * H_ * S_ * D_];

// ---------------------------------------------------------------------------
// QKV projection via bf16 split-precision tensor-core GEMM.
//   Y = X @ W + bias, fp32 in/out, internally x = hi + lo (bf16 each),
//   D = Ah*Bh + Ah*Bl + Al*Bh  (lo*lo dropped, ~2^-16 relative).
// Block tile 128x128x32, 256 threads (8 warps, 2x4), warp tile 64x32.
// blockIdx.z selects Q/K/V.
// ---------------------------------------------------------------------------
#define TBM 128
#define TBN 128
#define TBK 32
#define LDA (TBK + 8)     // A row stride in bf16 (pad -> conflict-free frags)
#define LDB (TBN + 8)     // B row stride in bf16

__device__ __forceinline__ void split_bf16(float x, __nv_bfloat16& h, __nv_bfloat16& l) {
    h = __float2bfloat16(x);
    l = __float2bfloat16(x - __bfloat162float(h));
}

__device__ __forceinline__ uint32_t pack2(const __nv_bfloat16* p0, const __nv_bfloat16* p1) {
    uint32_t lo = *(const unsigned short*)p0;
    uint32_t hi = *(const unsigned short*)p1;
    return lo | (hi << 16);
}

__device__ __forceinline__ void mma16816(float* d, const uint32_t* a, const uint32_t* b) {
    asm volatile(
        "mma.sync.aligned.m16n8k16.row.col.f32.bf16.bf16.f32 "
        "{%0,%1,%2,%3}, {%4,%5,%6,%7}, {%8,%9}, {%0,%1,%2,%3};\n"
        : "+f"(d[0]), "+f"(d[1]), "+f"(d[2]), "+f"(d[3])
        : "r"(a[0]), "r"(a[1]), "r"(a[2]), "r"(a[3]), "r"(b[0]), "r"(b[1]));
}

__global__ __launch_bounds__(256)
void qkv_mma(const float* __restrict__ X,
             const float* __restrict__ Wq, const float* __restrict__ bq,
             const float* __restrict__ Wk, const float* __restrict__ bk,
             const float* __restrict__ Wv, const float* __restrict__ bv)
{
    const int which = blockIdx.z;
    const float* __restrict__ W    = (which == 0) ? Wq : (which == 1) ? Wk : Wv;
    const float* __restrict__ bias = (which == 0) ? bq : (which == 1) ? bk : bv;
    float* __restrict__ out        = (which == 0) ? g_q : (which == 1) ? g_k : g_v;

    __shared__ __nv_bfloat16 Ah[TBM][LDA], Al[TBM][LDA];
    __shared__ __nv_bfloat16 Bh[TBK][LDB], Bl[TBK][LDB];

    const int m0 = blockIdx.y * TBM;
    const int n0 = blockIdx.x * TBN;
    const int tid  = threadIdx.x;
    const int warp = tid >> 5;
    const int lane = tid & 31;
    const int wm = (warp >> 2) * 64;   // 0 or 64
    const int wn = (warp & 3) * 32;    // 0,32,64,96

    float acc[4][4][4];
    #pragma unroll
    for (int i = 0; i < 4; i++)
        #pragma unroll
        for (int j = 0; j < 4; j++)
            #pragma unroll
            for (int r = 0; r < 4; r++) acc[i][j][r] = 0.f;

    // Register-staged prefetch buffers
    float4 ra[4], rb[4];

    // ---- load tile k0 = 0 into registers ----
    {
        #pragma unroll
        for (int u = 0; u < 4; u++) {
            const int idx = tid + u * 256;
            const int row = idx >> 3;           // 0..127
            const int kq  = idx & 7;            // 0..7 (float4 in k)
            ra[u] = *(const float4*)&X[(m0 + row) * E_ + kq * 4];
        }
        #pragma unroll
        for (int u = 0; u < 4; u++) {
            const int idx = tid + u * 256;
            const int kr = idx >> 5;            // 0..31 (k row)
            const int nq = idx & 31;            // 0..31 (float4 in n)
            rb[u] = *(const float4*)&W[kr * E_ + n0 + nq * 4];
        }
    }

    for (int k0 = 0; k0 < E_; k0 += TBK) {
        // ---- store staged registers to smem (with bf16 hi/lo split) ----
        #pragma unroll
        for (int u = 0; u < 4; u++) {
            const int idx = tid + u * 256;
            const int row = idx >> 3;
            const int kq  = (idx & 7) * 4;
            const float v[4] = {ra[u].x, ra[u].y, ra[u].z, ra[u].w};
            #pragma unroll
            for (int j = 0; j < 4; j++) {
                __nv_bfloat16 h, l;
                split_bf16(v[j], h, l);
                Ah[row][kq + j] = h;
                Al[row][kq + j] = l;
            }
        }
        #pragma unroll
        for (int u = 0; u < 4; u++) {
            const int idx = tid + u * 256;
            const int kr = idx >> 5;
            const int nq = (idx & 31) * 4;
            const float v[4] = {rb[u].x, rb[u].y, rb[u].z, rb[u].w};
            #pragma unroll
            for (int j = 0; j < 4; j++) {
                __nv_bfloat16 h, l;
                split_bf16(v[j], h, l);
                Bh[kr][nq + j] = h;
                Bl[kr][nq + j] = l;
            }
        }
        __syncthreads();

        // ---- prefetch next tile to registers ----
        if (k0 + TBK < E_) {
            const int kn = k0 + TBK;
            #pragma unroll
            for (int u = 0; u < 4; u++) {
                const int idx = tid + u * 256;
                const int row = idx >> 3;
                const int kq  = idx & 7;
                ra[u] = *(const float4*)&X[(m0 + row) * E_ + kn + kq * 4];
            }
            #pragma unroll
            for (int u = 0; u < 4; u++) {
                const int idx = tid + u * 256;
                const int kr = idx >> 5;
                const int nq = idx & 31;
                rb[u] = *(const float4*)&W[(kn + kr) * E_ + n0 + nq * 4];
            }
        }

        // ---- compute: 2 k-steps of 16 ----
        #pragma unroll
        for (int kk = 0; kk < TBK; kk += 16) {
            uint32_t ah[4][4], al[4][4];
            const int ar = wm + (lane >> 2);
            const int ac = kk + ((lane & 3) << 1);
            #pragma unroll
            for (int im = 0; im < 4; im++) {
                const int r = ar + im * 16;
                ah[im][0] = *(const uint32_t*)&Ah[r    ][ac    ];
                ah[im][1] = *(const uint32_t*)&Ah[r + 8][ac    ];
                ah[im][2] = *(const uint32_t*)&Ah[r    ][ac + 8];
                ah[im][3] = *(const uint32_t*)&Ah[r + 8][ac + 8];
                al[im][0] = *(const uint32_t*)&Al[r    ][ac    ];
                al[im][1] = *(const uint32_t*)&Al[r + 8][ac    ];
                al[im][2] = *(const uint32_t*)&Al[r    ][ac + 8];
                al[im][3] = *(const uint32_t*)&Al[r + 8][ac + 8];
            }
            uint32_t bhf[4][2], blf[4][2];
            const int bn = wn + (lane >> 2);
            const int bk = kk + ((lane & 3) << 1);
            #pragma unroll
            for (int jn = 0; jn < 4; jn++) {
                const int n = bn + jn * 8;
                bhf[jn][0] = pack2(&Bh[bk    ][n], &Bh[bk + 1][n]);
                bhf[jn][1] = pack2(&Bh[bk + 8][n], &Bh[bk + 9][n]);
                blf[jn][0] = pack2(&Bl[bk    ][n], &Bl[bk + 1][n]);
                blf[jn][1] = pack2(&Bl[bk + 8][n], &Bl[bk + 9][n]);
            }
            #pragma unroll
            for (int im = 0; im < 4; im++)
                #pragma unroll
                for (int jn = 0; jn < 4; jn++) {
                    mma16816(acc[im][jn], ah[im], bhf[jn]);
                    mma16816(acc[im][jn], ah[im], blf[jn]);
                    mma16816(acc[im][jn], al[im], bhf[jn]);
                }
        }
        __syncthreads();
    }

    // ---- epilogue: add bias, scatter to [B,H,S,D] ----
    #pragma unroll
    for (int jn = 0; jn < 4; jn++) {
        const int ncol = n0 + wn + jn * 8 + ((lane & 3) << 1);
        const int h = ncol >> 6;
        const int d = ncol & 63;
        const float b0v = bias[ncol];
        const float b1v = bias[ncol + 1];
        #pragma unroll
        for (int im = 0; im < 4; im++) {
            const int row = m0 + wm + im * 16 + (lane >> 2);
            const int bb = row >> 10;
            const int s  = row & (S_ - 1);
            float* base = out + (((bb * H_ + h) << 10) + s) * D_ + d;
            float2 v0 = make_float2(acc[im][jn][0] + b0v, acc[im][jn][1] + b1v);
            float2 v1 = make_float2(acc[im][jn][2] + b0v, acc[im][jn][3] + b1v);
            *(float2*)base = v0;
            *(float2*)(base + 8 * D_) = v1;   // row+8, same b/h
        }
    }
}

// ---------------------------------------------------------------------------
// Flash-style attention (fp32), with fully-invalid-block shortcut:
// rows >= len have uniform softmax -> output = column-mean of V over all S.
// ---------------------------------------------------------------------------
#define AT_SMEM_FLOATS (64*64 /*Qs*/ + 64*68 /*Kts*/ + 64*64 /*Vs*/ + 64*64 /*Ps*/)

__global__ __launch_bounds__(256)
void attn_kernel(const int* __restrict__ lens, float* __restrict__ out)
{
    extern __shared__ float smem[];
    float* Qs  = smem;                         // [64][64]
    float* Kts = Qs  + 64 * 64;                // [64][68]  K transposed
    float* Vs  = Kts + 64 * 68;                // [64][64]
    float* Ps  = Vs  + 64 * 64;                // [64][64]

    const int bh = blockIdx.y;
    const int b  = bh >> 4;
    const int h  = bh & (H_ - 1);
    const int len = lens[b];
    const int q0 = blockIdx.x * 64;

    const float* __restrict__ Q = g_q + bh * S_ * D_;
    const float* __restrict__ K = g_k + bh * S_ * D_;
    const float* __restrict__ V = g_v + bh * S_ * D_;

    const int tid = threadIdx.x;

    // ---- Shortcut: every query row in this block is invalid ----
    if (q0 >= len) {
        const int col = tid & 63;
        const int grp = tid >> 6;      // 0..3
        float a = 0.f;
        for (int t = grp; t < S_; t += 4) a += V[t * D_ + col];
        smem[grp * 64 + col] = a;
        __syncthreads();
        const float m = (smem[0 * 64 + col] + smem[1 * 64 + col] +
                         smem[2 * 64 + col] + smem[3 * 64 + col]) * (1.0f / 1024.0f);
        for (int r = grp; r < 64; r += 4)
            out[(b * S_ + q0 + r) * E_ + h * D_ + col] = m;
        return;
    }

    const int tx = tid & 15;
    const int ty = tid >> 4;

    // Load Q tile (64 x 64)
    #pragma unroll
    for (int u = 0; u < 4; u++) {
        const int idx = tid + u * 256;
        const int r = idx >> 4, dq = idx & 15;
        *(float4*)&Qs[r * 64 + dq * 4] = *(const float4*)&Q[(q0 + r) * D_ + dq * 4];
    }

    float m_i[4], l_i[4], o[4][4];
    #pragma unroll
    for (int i = 0; i < 4; i++) {
        m_i[i] = -CUDART_INF_F;
        l_i[i] = 0.f;
        #pragma unroll
        for (int j = 0; j < 4; j++) o[i][j] = 0.f;
    }

    const bool all_valid = (q0 + 64 <= len);
    const int kend = all_valid ? ((len + 63) & ~63) : S_;
    const float scale = 0.125f;  // 1/sqrt(D)

    for (int t0 = 0; t0 < kend; t0 += 64) {
        __syncthreads();

        #pragma unroll
        for (int u = 0; u < 4; u++) {
            const int idx = tid + u * 256;
            const int r = idx >> 4, dq = idx & 15;
            float4 kv = *(const float4*)&K[(t0 + r) * D_ + dq * 4];
            Kts[(dq * 4 + 0) * 68 + r] = kv.x;
            Kts[(dq * 4 + 1) * 68 + r] = kv.y;
            Kts[(dq * 4 + 2) * 68 + r] = kv.z;
            Kts[(dq * 4 + 3) * 68 + r] = kv.w;
            *(float4*)&Vs[r * 64 + dq * 4] = *(const float4*)&V[(t0 + r) * D_ + dq * 4];
        }
        __syncthreads();

        float sc[4][4] = {};
        #pragma unroll 16
        for (int d = 0; d < 64; d++) {
            float a[4];
            #pragma unroll
            for (int i = 0; i < 4; i++) a[i] = Qs[(ty * 4 + i) * 64 + d];
            float4 b4 = *(const float4*)&Kts[d * 68 + tx * 4];
            #pragma unroll
            for (int i = 0; i < 4; i++) {
                sc[i][0] += a[i] * b4.x;
                sc[i][1] += a[i] * b4.y;
                sc[i][2] += a[i] * b4.z;
                sc[i][3] += a[i] * b4.w;
            }
        }

        #pragma unroll
        for (int i = 0; i < 4; i++) {
            const bool rv = (q0 + ty * 4 + i) < len;
            #pragma unroll
            for (int j = 0; j < 4; j++) {
                const bool cv = (t0 + tx * 4 + j) < len;
                sc[i][j] = (rv && cv) ? sc[i][j] * scale : -1e9f;
            }
        }

        float alpha[4];
        #pragma unroll
        for (int i = 0; i < 4; i++) {
            float v = fmaxf(fmaxf(sc[i][0], sc[i][1]), fmaxf(sc[i][2], sc[i][3]));
            #pragma unroll
            for (int off = 8; off > 0; off >>= 1)
                v = fmaxf(v, __shfl_xor_sync(0xffffffffu, v, off, 16));
            const float mnew = fmaxf(m_i[i], v);
            alpha[i] = __expf(m_i[i] - mnew);
            m_i[i] = mnew;

            float s = 0.f;
            #pragma unroll
            for (int j = 0; j < 4; j++) {
                const float p = __expf(sc[i][j] - mnew);
                sc[i][j] = p;
                s += p;
            }
            #pragma unroll
            for (int off = 8; off > 0; off >>= 1)
                s += __shfl_xor_sync(0xffffffffu, s, off, 16);
            l_i[i] = l_i[i] * alpha[i] + s;
            #pragma unroll
            for (int j = 0; j < 4; j++) o[i][j] *= alpha[i];
        }

        #pragma unroll
        for (int i = 0; i < 4; i++) {
            float4 p4 = make_float4(sc[i][0], sc[i][1], sc[i][2], sc[i][3]);
            *(float4*)&Ps[(ty * 4 + i) * 64 + tx * 4] = p4;
        }
        __syncthreads();

        #pragma unroll 16
        for (int t = 0; t < 64; t++) {
            float p[4];
            #pragma unroll
            for (int i = 0; i < 4; i++) p[i] = Ps[(ty * 4 + i) * 64 + t];
            float4 v4 = *(const float4*)&Vs[t * 64 + tx * 4];
            #pragma unroll
            for (int i = 0; i < 4; i++) {
                o[i][0] += p[i] * v4.x;
                o[i][1] += p[i] * v4.y;
                o[i][2] += p[i] * v4.z;
                o[i][3] += p[i] * v4.w;
            }
        }
    }

    #pragma unroll
    for (int i = 0; i < 4; i++) {
        const float inv = 1.f / l_i[i];
        const int s = q0 + ty * 4 + i;
        float4 r;
        r.x = o[i][0] * inv;
        r.y = o[i][1] * inv;
        r.z = o[i][2] * inv;
        r.w = o[i][3] * inv;
        *(float4*)&out[(b * S_ + s) * E_ + h * D_ + tx * 4] = r;
    }
}

// ---------------------------------------------------------------------------
extern "C" void kernel_launch(void* const* d_in, const int* in_sizes, int n_in,
                              void* d_out, int out_size)
{
    const float* x   = (const float*)d_in[0];
    const float* Wq  = (const float*)d_in[1];
    const float* bq  = (const float*)d_in[2];
    const float* Wk  = (const float*)d_in[3];
    const float* bk  = (const float*)d_in[4];
    const float* Wv  = (const float*)d_in[5];
    const float* bv  = (const float*)d_in[6];
    const int*  lens = (const int*)d_in[7];
    float* out = (float*)d_out;

    // Projections: grid (N/128, M/128, 3), tensor-core path
    dim3 ggrid(E_ / TBN, M_ / TBM, 3);
    qkv_mma<<<ggrid, 256>>>(x, Wq, bq, Wk, bk, Wv, bv);

    // Attention: grid (S/64 query tiles, B*H)
    const int smem_bytes = AT_SMEM_FLOATS * (int)sizeof(float);
    cudaFuncSetAttribute(attn_kernel,
                         cudaFuncAttributeMaxDynamicSharedMemorySize, smem_bytes);
    dim3 agrid(S_ / 64, B_ * H_);
    attn_kernel<<<agrid, 256, smem_bytes>>>(lens, out);
}

// round 4
// speedup vs baseline: 2.2919x; 1.4087x over previous
#include <cuda_runtime.h>
#include <cuda_bf16.h>
#include <math_constants.h>
#include <cstdint>

// Problem constants (fixed by the dataset)
#define B_  4
#define S_  1024
#define E_  1024
#define H_  16
#define D_  64
#define M_  (B_ * S_)

// Split-bf16 scratch (hi + lo). Q/K row-major [bh][s][d]; V transposed [bh][d][s].
__device__ __nv_bfloat16 g_qh[B_*H_*S_*D_], g_ql[B_*H_*S_*D_];
__device__ __nv_bfloat16 g_kh[B_*H_*S_*D_], g_kl[B_*H_*S_*D_];
__device__ __nv_bfloat16 g_vth[B_*H_*S_*D_], g_vtl[B_*H_*S_*D_];

__device__ __forceinline__ void mma16816(float* d, const uint32_t* a, const uint32_t* b) {
    asm volatile(
        "mma.sync.aligned.m16n8k16.row.col.f32.bf16.bf16.f32 "
        "{%0,%1,%2,%3}, {%4,%5,%6,%7}, {%8,%9}, {%0,%1,%2,%3};\n"
        : "+f"(d[0]), "+f"(d[1]), "+f"(d[2]), "+f"(d[3])
        : "r"(a[0]), "r"(a[1]), "r"(a[2]), "r"(a[3]), "r"(b[0]), "r"(b[1]));
}

__device__ __forceinline__ uint32_t pack_bf2(__nv_bfloat16 lo, __nv_bfloat16 hi) {
    uint32_t l = *(const unsigned short*)&lo;
    uint32_t h = *(const unsigned short*)&hi;
    return l | (h << 16);
}

__device__ __forceinline__ void split_bf16(float x, __nv_bfloat16& h, __nv_bfloat16& l) {
    h = __float2bfloat16(x);
    l = __float2bfloat16(x - __bfloat162float(h));
}

// ---------------------------------------------------------------------------
// QKV projection: fp32 in, split-bf16 out (hi/lo). 3-pass bf16 MMA internally.
// Block tile 128x128x32, 256 threads, warp tile 64x32. blockIdx.z = Q/K/V.
// ---------------------------------------------------------------------------
#define TBM 128
#define TBN 128
#define TBK 32
#define LDA (TBK + 8)
#define LDB (TBN + 8)

__device__ __forceinline__ uint32_t pack2(const __nv_bfloat16* p0, const __nv_bfloat16* p1) {
    uint32_t lo = *(const unsigned short*)p0;
    uint32_t hi = *(const unsigned short*)p1;
    return lo | (hi << 16);
}

__global__ __launch_bounds__(256)
void qkv_mma(const float* __restrict__ X,
             const float* __restrict__ Wq, const float* __restrict__ bq,
             const float* __restrict__ Wk, const float* __restrict__ bk,
             const float* __restrict__ Wv, const float* __restrict__ bv)
{
    const int which = blockIdx.z;
    const float* __restrict__ W    = (which == 0) ? Wq : (which == 1) ? Wk : Wv;
    const float* __restrict__ bias = (which == 0) ? bq : (which == 1) ? bk : bv;

    __shared__ __nv_bfloat16 Ah[TBM][LDA], Al[TBM][LDA];
    __shared__ __nv_bfloat16 Bh[TBK][LDB], Bl[TBK][LDB];

    const int m0 = blockIdx.y * TBM;
    const int n0 = blockIdx.x * TBN;
    const int tid  = threadIdx.x;
    const int warp = tid >> 5;
    const int lane = tid & 31;
    const int wm = (warp >> 2) * 64;
    const int wn = (warp & 3) * 32;

    float acc[4][4][4];
    #pragma unroll
    for (int i = 0; i < 4; i++)
        #pragma unroll
        for (int j = 0; j < 4; j++)
            #pragma unroll
            for (int r = 0; r < 4; r++) acc[i][j][r] = 0.f;

    float4 ra[4], rb[4];
    {
        #pragma unroll
        for (int u = 0; u < 4; u++) {
            const int idx = tid + u * 256;
            const int row = idx >> 3, kq = idx & 7;
            ra[u] = *(const float4*)&X[(m0 + row) * E_ + kq * 4];
        }
        #pragma unroll
        for (int u = 0; u < 4; u++) {
            const int idx = tid + u * 256;
            const int kr = idx >> 5, nq = idx & 31;
            rb[u] = *(const float4*)&W[kr * E_ + n0 + nq * 4];
        }
    }

    for (int k0 = 0; k0 < E_; k0 += TBK) {
        #pragma unroll
        for (int u = 0; u < 4; u++) {
            const int idx = tid + u * 256;
            const int row = idx >> 3;
            const int kq  = (idx & 7) * 4;
            const float v[4] = {ra[u].x, ra[u].y, ra[u].z, ra[u].w};
            #pragma unroll
            for (int j = 0; j < 4; j++) {
                __nv_bfloat16 h, l;
                split_bf16(v[j], h, l);
                Ah[row][kq + j] = h;
                Al[row][kq + j] = l;
            }
        }
        #pragma unroll
        for (int u = 0; u < 4; u++) {
            const int idx = tid + u * 256;
            const int kr = idx >> 5;
            const int nq = (idx & 31) * 4;
            const float v[4] = {rb[u].x, rb[u].y, rb[u].z, rb[u].w};
            #pragma unroll
            for (int j = 0; j < 4; j++) {
                __nv_bfloat16 h, l;
                split_bf16(v[j], h, l);
                Bh[kr][nq + j] = h;
                Bl[kr][nq + j] = l;
            }
        }
        __syncthreads();

        if (k0 + TBK < E_) {
            const int kn = k0 + TBK;
            #pragma unroll
            for (int u = 0; u < 4; u++) {
                const int idx = tid + u * 256;
                const int row = idx >> 3, kq = idx & 7;
                ra[u] = *(const float4*)&X[(m0 + row) * E_ + kn + kq * 4];
            }
            #pragma unroll
            for (int u = 0; u < 4; u++) {
                const int idx = tid + u * 256;
                const int kr = idx >> 5, nq = idx & 31;
                rb[u] = *(const float4*)&W[(kn + kr) * E_ + n0 + nq * 4];
            }
        }

        #pragma unroll
        for (int kk = 0; kk < TBK; kk += 16) {
            uint32_t ah[4][4], al[4][4];
            const int ar = wm + (lane >> 2);
            const int ac = kk + ((lane & 3) << 1);
            #pragma unroll
            for (int im = 0; im < 4; im++) {
                const int r = ar + im * 16;
                ah[im][0] = *(const uint32_t*)&Ah[r    ][ac    ];
                ah[im][1] = *(const uint32_t*)&Ah[r + 8][ac    ];
                ah[im][2] = *(const uint32_t*)&Ah[r    ][ac + 8];
                ah[im][3] = *(const uint32_t*)&Ah[r + 8][ac + 8];
                al[im][0] = *(const uint32_t*)&Al[r    ][ac    ];
                al[im][1] = *(const uint32_t*)&Al[r + 8][ac    ];
                al[im][2] = *(const uint32_t*)&Al[r    ][ac + 8];
                al[im][3] = *(const uint32_t*)&Al[r + 8][ac + 8];
            }
            uint32_t bhf[4][2], blf[4][2];
            const int bn = wn + (lane >> 2);
            const int bk = kk + ((lane & 3) << 1);
            #pragma unroll
            for (int jn = 0; jn < 4; jn++) {
                const int n = bn + jn * 8;
                bhf[jn][0] = pack2(&Bh[bk    ][n], &Bh[bk + 1][n]);
                bhf[jn][1] = pack2(&Bh[bk + 8][n], &Bh[bk + 9][n]);
                blf[jn][0] = pack2(&Bl[bk    ][n], &Bl[bk + 1][n]);
                blf[jn][1] = pack2(&Bl[bk + 8][n], &Bl[bk + 9][n]);
            }
            #pragma unroll
            for (int im = 0; im < 4; im++)
                #pragma unroll
                for (int jn = 0; jn < 4; jn++) {
                    mma16816(acc[im][jn], ah[im], bhf[jn]);
                    mma16816(acc[im][jn], ah[im], blf[jn]);
                    mma16816(acc[im][jn], al[im], bhf[jn]);
                }
        }
        __syncthreads();
    }

    // ---- epilogue: add bias, split to bf16 hi/lo, write scratch ----
    if (which < 2) {
        __nv_bfloat16* __restrict__ oh = (which == 0) ? g_qh : g_kh;
        __nv_bfloat16* __restrict__ ol = (which == 0) ? g_ql : g_kl;
        #pragma unroll
        for (int jn = 0; jn < 4; jn++) {
            const int ncol = n0 + wn + jn * 8 + ((lane & 3) << 1);
            const int hh = ncol >> 6;
            const int d  = ncol & 63;
            const float b0v = bias[ncol], b1v = bias[ncol + 1];
            #pragma unroll
            for (int im = 0; im < 4; im++) {
                const int row = m0 + wm + im * 16 + (lane >> 2);
                const int bb = row >> 10;
                const int s  = row & (S_ - 1);
                const int base = ((bb * H_ + hh) * S_ + s) * D_ + d;
                __nv_bfloat16 h0, l0, h1, l1;
                split_bf16(acc[im][jn][0] + b0v, h0, l0);
                split_bf16(acc[im][jn][1] + b1v, h1, l1);
                *(uint32_t*)&oh[base] = pack_bf2(h0, h1);
                *(uint32_t*)&ol[base] = pack_bf2(l0, l1);
                split_bf16(acc[im][jn][2] + b0v, h0, l0);
                split_bf16(acc[im][jn][3] + b1v, h1, l1);
                *(uint32_t*)&oh[base + 8 * D_] = pack_bf2(h0, h1);
                *(uint32_t*)&ol[base + 8 * D_] = pack_bf2(l0, l1);
            }
        }
    } else {
        // V: scatter-transpose to [bh][d][s]
        #pragma unroll
        for (int jn = 0; jn < 4; jn++) {
            const int ncol = n0 + wn + jn * 8 + ((lane & 3) << 1);
            const int hh = ncol >> 6;
            const int d  = ncol & 63;
            const float b0v = bias[ncol], b1v = bias[ncol + 1];
            #pragma unroll
            for (int im = 0; im < 4; im++) {
                const int row = m0 + wm + im * 16 + (lane >> 2);
                const int bb = row >> 10;
                const int s  = row & (S_ - 1);
                const int vb = ((bb * H_ + hh) * D_ + d) * S_ + s;
                __nv_bfloat16 h, l;
                split_bf16(acc[im][jn][0] + b0v, h, l);
                g_vth[vb] = h;            g_vtl[vb] = l;
                split_bf16(acc[im][jn][1] + b1v, h, l);
                g_vth[vb + S_] = h;       g_vtl[vb + S_] = l;
                split_bf16(acc[im][jn][2] + b0v, h, l);
                g_vth[vb + 8] = h;        g_vtl[vb + 8] = l;
                split_bf16(acc[im][jn][3] + b1v, h, l);
                g_vth[vb + S_ + 8] = h;   g_vtl[vb + S_ + 8] = l;
            }
        }
    }
}

// ---------------------------------------------------------------------------
// MMA flash attention. 128 threads (4 warps), 64 q rows per block.
// Split-bf16 3-pass MMAs for QK^T and PV; fp32 online softmax in registers.
// ---------------------------------------------------------------------------
#define ALD 72                 // smem row stride in bf16 (64 + 8 pad)
#define AT_SMEM_BYTES (6 * 64 * ALD * 2)

__global__ __launch_bounds__(128)
void attn_mma(const int* __restrict__ lens, float* __restrict__ out)
{
    extern __shared__ char smem_raw[];
    __nv_bfloat16* Qh  = (__nv_bfloat16*)smem_raw;
    __nv_bfloat16* Ql  = Qh  + 64 * ALD;
    __nv_bfloat16* Kh  = Ql  + 64 * ALD;
    __nv_bfloat16* Kl  = Kh  + 64 * ALD;
    __nv_bfloat16* Vth = Kl  + 64 * ALD;   // [d][t]
    __nv_bfloat16* Vtl = Vth + 64 * ALD;

    const int bh = blockIdx.y;
    const int b  = bh >> 4;
    const int h  = bh & (H_ - 1);
    const int len = lens[b];
    const int q0 = blockIdx.x * 64;
    const int tid = threadIdx.x;

    // ---- Shortcut: whole block invalid -> uniform mean of V ----
    if (q0 >= len) {
        float* red = (float*)smem_raw;
        const int d = tid & 63;
        const int half = tid >> 6;
        const uint4* ph = (const uint4*)(g_vth + (bh * D_ + d) * S_) + half * 64;
        const uint4* pl = (const uint4*)(g_vtl + (bh * D_ + d) * S_) + half * 64;
        float a = 0.f;
        for (int i = 0; i < 64; i++) {
            uint4 xh = ph[i], xl = pl[i];
            const __nv_bfloat162* eh = (const __nv_bfloat162*)&xh;
            const __nv_bfloat162* el = (const __nv_bfloat162*)&xl;
            #pragma unroll
            for (int e = 0; e < 4; e++) {
                float2 fh = __bfloat1622float2(eh[e]);
                float2 fl = __bfloat1622float2(el[e]);
                a += fh.x + fh.y + fl.x + fl.y;
            }
        }
        red[half * 64 + d] = a;
        __syncthreads();
        const float m = (red[d] + red[64 + d]) * (1.0f / 1024.0f);
        for (int r = half; r < 64; r += 2)
            out[(b * S_ + q0 + r) * E_ + h * D_ + d] = m;
        return;
    }

    const int warp = tid >> 5;
    const int lane = tid & 31;
    const int wm = warp * 16;

    const size_t qoff = (size_t)bh * S_ * D_;

    // Load Q tile (64x64 bf16 x2) into smem
    #pragma unroll
    for (int u = 0; u < 4; u++) {
        const int idx = tid + u * 128;
        const int r = idx >> 3, seg = idx & 7;
        *(uint4*)&Qh[r * ALD + seg * 8] = *(const uint4*)&g_qh[qoff + (q0 + r) * D_ + seg * 8];
        *(uint4*)&Ql[r * ALD + seg * 8] = *(const uint4*)&g_ql[qoff + (q0 + r) * D_ + seg * 8];
    }

    float m0 = -CUDART_INF_F, m1 = -CUDART_INF_F, l0 = 0.f, l1 = 0.f;
    float o[8][4];
    #pragma unroll
    for (int j = 0; j < 8; j++)
        #pragma unroll
        for (int e = 0; e < 4; e++) o[j][e] = 0.f;

    const bool all_valid = (q0 + 64 <= len);
    const int kend = all_valid ? ((len + 63) & ~63) : S_;
    const float scale = 0.125f;

    const int r0g = q0 + wm + (lane >> 2);
    const int r1g = r0g + 8;
    const bool rv0 = r0g < len, rv1 = r1g < len;

    for (int t0 = 0; t0 < kend; t0 += 64) {
        __syncthreads();
        // Load K tile [t][d] and Vt tile [d][t]
        #pragma unroll
        for (int u = 0; u < 4; u++) {
            const int idx = tid + u * 128;
            const int r = idx >> 3, seg = idx & 7;
            *(uint4*)&Kh[r * ALD + seg * 8]  = *(const uint4*)&g_kh[qoff + (t0 + r) * D_ + seg * 8];
            *(uint4*)&Kl[r * ALD + seg * 8]  = *(const uint4*)&g_kl[qoff + (t0 + r) * D_ + seg * 8];
            *(uint4*)&Vth[r * ALD + seg * 8] = *(const uint4*)&g_vth[(size_t)(bh * D_ + r) * S_ + t0 + seg * 8];
            *(uint4*)&Vtl[r * ALD + seg * 8] = *(const uint4*)&g_vtl[(size_t)(bh * D_ + r) * S_ + t0 + seg * 8];
        }
        __syncthreads();

        // ---- S = Q K^T ----
        float sc[8][4];
        #pragma unroll
        for (int j = 0; j < 8; j++)
            #pragma unroll
            for (int e = 0; e < 4; e++) sc[j][e] = 0.f;

        #pragma unroll
        for (int kk = 0; kk < 64; kk += 16) {
            uint32_t ah[4], al[4];
            const int ar = wm + (lane >> 2);
            const int ac = kk + ((lane & 3) << 1);
            ah[0] = *(const uint32_t*)&Qh[ ar      * ALD + ac    ];
            ah[1] = *(const uint32_t*)&Qh[(ar + 8) * ALD + ac    ];
            ah[2] = *(const uint32_t*)&Qh[ ar      * ALD + ac + 8];
            ah[3] = *(const uint32_t*)&Qh[(ar + 8) * ALD + ac + 8];
            al[0] = *(const uint32_t*)&Ql[ ar      * ALD + ac    ];
            al[1] = *(const uint32_t*)&Ql[(ar + 8) * ALD + ac    ];
            al[2] = *(const uint32_t*)&Ql[ ar      * ALD + ac + 8];
            al[3] = *(const uint32_t*)&Ql[(ar + 8) * ALD + ac + 8];
            #pragma unroll
            for (int j = 0; j < 8; j++) {
                const int br = j * 8 + (lane >> 2);
                const int bc = kk + ((lane & 3) << 1);
                uint32_t bhf[2], blf[2];
                bhf[0] = *(const uint32_t*)&Kh[br * ALD + bc    ];
                bhf[1] = *(const uint32_t*)&Kh[br * ALD + bc + 8];
                blf[0] = *(const uint32_t*)&Kl[br * ALD + bc    ];
                blf[1] = *(const uint32_t*)&Kl[br * ALD + bc + 8];
                mma16816(sc[j], ah, bhf);
                mma16816(sc[j], ah, blf);
                mma16816(sc[j], al, bhf);
            }
        }

        // ---- mask + scale ----
        #pragma unroll
        for (int j = 0; j < 8; j++) {
            const int c0 = t0 + j * 8 + ((lane & 3) << 1);
            const bool cv0 = c0 < len, cv1 = (c0 + 1) < len;
            sc[j][0] = (rv0 && cv0) ? sc[j][0] * scale : -1e9f;
            sc[j][1] = (rv0 && cv1) ? sc[j][1] * scale : -1e9f;
            sc[j][2] = (rv1 && cv0) ? sc[j][2] * scale : -1e9f;
            sc[j][3] = (rv1 && cv1) ? sc[j][3] * scale : -1e9f;
        }

        // ---- online softmax (quad shuffles: lanes sharing a row) ----
        float vm0 = -CUDART_INF_F, vm1 = -CUDART_INF_F;
        #pragma unroll
        for (int j = 0; j < 8; j++) {
            vm0 = fmaxf(vm0, fmaxf(sc[j][0], sc[j][1]));
            vm1 = fmaxf(vm1, fmaxf(sc[j][2], sc[j][3]));
        }
        vm0 = fmaxf(vm0, __shfl_xor_sync(0xffffffffu, vm0, 1));
        vm0 = fmaxf(vm0, __shfl_xor_sync(0xffffffffu, vm0, 2));
        vm1 = fmaxf(vm1, __shfl_xor_sync(0xffffffffu, vm1, 1));
        vm1 = fmaxf(vm1, __shfl_xor_sync(0xffffffffu, vm1, 2));
        const float mn0 = fmaxf(m0, vm0);
        const float mn1 = fmaxf(m1, vm1);
        const float al0 = __expf(m0 - mn0);
        const float al1 = __expf(m1 - mn1);
        m0 = mn0; m1 = mn1;

        float s0 = 0.f, s1 = 0.f;
        #pragma unroll
        for (int j = 0; j < 8; j++) {
            sc[j][0] = __expf(sc[j][0] - mn0); s0 += sc[j][0];
            sc[j][1] = __expf(sc[j][1] - mn0); s0 += sc[j][1];
            sc[j][2] = __expf(sc[j][2] - mn1); s1 += sc[j][2];
            sc[j][3] = __expf(sc[j][3] - mn1); s1 += sc[j][3];
        }
        s0 += __shfl_xor_sync(0xffffffffu, s0, 1);
        s0 += __shfl_xor_sync(0xffffffffu, s0, 2);
        s1 += __shfl_xor_sync(0xffffffffu, s1, 1);
        s1 += __shfl_xor_sync(0xffffffffu, s1, 2);
        l0 = l0 * al0 + s0;
        l1 = l1 * al1 + s1;
        #pragma unroll
        for (int j = 0; j < 8; j++) {
            o[j][0] *= al0; o[j][1] *= al0;
            o[j][2] *= al1; o[j][3] *= al1;
        }

        // ---- O += P V ----
        #pragma unroll
        for (int kp = 0; kp < 4; kp++) {
            const int j0 = kp * 2, j1 = kp * 2 + 1;
            uint32_t pah[4], pal[4];
            {
                __nv_bfloat16 hx, lx, hy, ly;
                split_bf16(sc[j0][0], hx, lx); split_bf16(sc[j0][1], hy, ly);
                pah[0] = pack_bf2(hx, hy); pal[0] = pack_bf2(lx, ly);
                split_bf16(sc[j0][2], hx, lx); split_bf16(sc[j0][3], hy, ly);
                pah[1] = pack_bf2(hx, hy); pal[1] = pack_bf2(lx, ly);
                split_bf16(sc[j1][0], hx, lx); split_bf16(sc[j1][1], hy, ly);
                pah[2] = pack_bf2(hx, hy); pal[2] = pack_bf2(lx, ly);
                split_bf16(sc[j1][2], hx, lx); split_bf16(sc[j1][3], hy, ly);
                pah[3] = pack_bf2(hx, hy); pal[3] = pack_bf2(lx, ly);
            }
            #pragma unroll
            for (int j = 0; j < 8; j++) {
                const int br = j * 8 + (lane >> 2);          // d index
                const int bc = kp * 16 + ((lane & 3) << 1);  // t index
                uint32_t bhf[2], blf[2];
                bhf[0] = *(const uint32_t*)&Vth[br * ALD + bc    ];
                bhf[1] = *(const uint32_t*)&Vth[br * ALD + bc + 8];
                blf[0] = *(const uint32_t*)&Vtl[br * ALD + bc    ];
                blf[1] = *(const uint32_t*)&Vtl[br * ALD + bc + 8];
                mma16816(o[j], pah, bhf);
                mma16816(o[j], pah, blf);
                mma16816(o[j], pal, bhf);
            }
        }
    }

    // ---- epilogue ----
    const float inv0 = 1.f / l0;
    const float inv1 = 1.f / l1;
    #pragma unroll
    for (int j = 0; j < 8; j++) {
        const int d = j * 8 + ((lane & 3) << 1);
        float2 w0 = make_float2(o[j][0] * inv0, o[j][1] * inv0);
        float2 w1 = make_float2(o[j][2] * inv1, o[j][3] * inv1);
        *(float2*)&out[(b * S_ + r0g) * E_ + h * D_ + d] = w0;
        *(float2*)&out[(b * S_ + r1g) * E_ + h * D_ + d] = w1;
    }
}

// ---------------------------------------------------------------------------
extern "C" void kernel_launch(void* const* d_in, const int* in_sizes, int n_in,
                              void* d_out, int out_size)
{
    const float* x   = (const float*)d_in[0];
    const float* Wq  = (const float*)d_in[1];
    const float* bq  = (const float*)d_in[2];
    const float* Wk  = (const float*)d_in[3];
    const float* bk  = (const float*)d_in[4];
    const float* Wv  = (const float*)d_in[5];
    const float* bv  = (const float*)d_in[6];
    const int*  lens = (const int*)d_in[7];
    float* out = (float*)d_out;

    dim3 ggrid(E_ / TBN, M_ / TBM, 3);
    qkv_mma<<<ggrid, 256>>>(x, Wq, bq, Wk, bk, Wv, bv);

    cudaFuncSetAttribute(attn_mma,
                         cudaFuncAttributeMaxDynamicSharedMemorySize, AT_SMEM_BYTES);
    dim3 agrid(S_ / 64, B_ * H_);
    attn_mma<<<agrid, 128, AT_SMEM_BYTES>>>(lens, out);
}

// round 5
// speedup vs baseline: 2.4882x; 1.0856x over previous
#include <cuda_runtime.h>
#include <cuda_bf16.h>
#include <math_constants.h>
#include <cstdint>

// Problem constants (fixed by the dataset)
#define B_  4
#define S_  1024
#define E_  1024
#define H_  16
#define D_  64
#define M_  (B_ * S_)

// Pre-split inputs (bf16 hi/lo). X row-major [m][k]; W transposed [which][n][k].
__device__ __nv_bfloat16 g_xh[M_*E_],  g_xl[M_*E_];
__device__ __nv_bfloat16 g_wth[3*E_*E_], g_wtl[3*E_*E_];

// Split-bf16 Q/K/V scratch. Q/K row-major [bh][s][d]; V transposed [bh][d][s].
__device__ __nv_bfloat16 g_qh[B_*H_*S_*D_], g_ql[B_*H_*S_*D_];
__device__ __nv_bfloat16 g_kh[B_*H_*S_*D_], g_kl[B_*H_*S_*D_];
__device__ __nv_bfloat16 g_vth[B_*H_*S_*D_], g_vtl[B_*H_*S_*D_];

__device__ __forceinline__ void mma16816(float* d, const uint32_t* a, const uint32_t* b) {
    asm volatile(
        "mma.sync.aligned.m16n8k16.row.col.f32.bf16.bf16.f32 "
        "{%0,%1,%2,%3}, {%4,%5,%6,%7}, {%8,%9}, {%0,%1,%2,%3};\n"
        : "+f"(d[0]), "+f"(d[1]), "+f"(d[2]), "+f"(d[3])
        : "r"(a[0]), "r"(a[1]), "r"(a[2]), "r"(a[3]), "r"(b[0]), "r"(b[1]));
}

__device__ __forceinline__ uint32_t pack_bf2(__nv_bfloat16 lo, __nv_bfloat16 hi) {
    uint32_t l = *(const unsigned short*)&lo;
    uint32_t h = *(const unsigned short*)&hi;
    return l | (h << 16);
}

__device__ __forceinline__ void split_bf16(float x, __nv_bfloat16& h, __nv_bfloat16& l) {
    h = __float2bfloat16(x);
    l = __float2bfloat16(x - __bfloat162float(h));
}

// ---------------------------------------------------------------------------
// Pre-pass 1: split X to bf16 hi/lo. 8 floats per thread.
// ---------------------------------------------------------------------------
__global__ __launch_bounds__(256)
void xsplit(const float* __restrict__ X)
{
    const int i = (blockIdx.x * 256 + threadIdx.x) * 8;
    float4 a = *(const float4*)&X[i];
    float4 b = *(const float4*)&X[i + 4];
    const float v[8] = {a.x, a.y, a.z, a.w, b.x, b.y, b.z, b.w};
    __nv_bfloat16 h[8], l[8];
    #pragma unroll
    for (int j = 0; j < 8; j++) split_bf16(v[j], h[j], l[j]);
    *(uint4*)&g_xh[i] = *(const uint4*)h;
    *(uint4*)&g_xl[i] = *(const uint4*)l;
}

// ---------------------------------------------------------------------------
// Pre-pass 2: transpose + split W -> [n][k] bf16 hi/lo. Tiled 32x32.
// blockIdx.z selects Q/K/V weight.
// ---------------------------------------------------------------------------
__global__ __launch_bounds__(256)
void wsplit(const float* __restrict__ Wq, const float* __restrict__ Wk,
            const float* __restrict__ Wv)
{
    const int which = blockIdx.z;
    const float* __restrict__ W = (which == 0) ? Wq : (which == 1) ? Wk : Wv;
    __nv_bfloat16* __restrict__ oh = g_wth + which * E_ * E_;
    __nv_bfloat16* __restrict__ ol = g_wtl + which * E_ * E_;

    __shared__ float tile[32][33];
    const int tx = threadIdx.x, ty = threadIdx.y;   // block (32, 8)
    {
        const int n = blockIdx.x * 32 + tx;
        const int k = blockIdx.y * 32 + ty;
        #pragma unroll
        for (int j = 0; j < 32; j += 8)
            tile[ty + j][tx] = W[(k + j) * E_ + n];
    }
    __syncthreads();
    {
        const int k = blockIdx.y * 32 + tx;
        const int n = blockIdx.x * 32 + ty;
        #pragma unroll
        for (int j = 0; j < 32; j += 8) {
            __nv_bfloat16 h, l;
            split_bf16(tile[tx][ty + j], h, l);
            oh[(n + j) * E_ + k] = h;
            ol[(n + j) * E_ + k] = l;
        }
    }
}

// ---------------------------------------------------------------------------
// QKV projection GEMM: pre-split bf16 in, split-bf16 scratch out.
// Block tile 128x128x32, 256 threads, warp tile 64x32. blockIdx.z = Q/K/V.
// Both A and B smem tiles are [outer][k], stride 40 -> direct u32 frag loads.
// ---------------------------------------------------------------------------
#define TBM 128
#define TBN 128
#define TBK 32
#define LDT 40          // tile row stride in bf16 (32 + 8 pad)

__global__ __launch_bounds__(256)
void qkv_mma(const float* __restrict__ bq, const float* __restrict__ bk,
             const float* __restrict__ bv)
{
    const int which = blockIdx.z;
    const float* __restrict__ bias = (which == 0) ? bq : (which == 1) ? bk : bv;
    const __nv_bfloat16* __restrict__ Wh = g_wth + which * E_ * E_;
    const __nv_bfloat16* __restrict__ Wl = g_wtl + which * E_ * E_;

    __shared__ __nv_bfloat16 Ah[TBM][LDT], Al[TBM][LDT];
    __shared__ __nv_bfloat16 Bh[TBN][LDT], Bl[TBN][LDT];

    const int m0 = blockIdx.y * TBM;
    const int n0 = blockIdx.x * TBN;
    const int tid  = threadIdx.x;
    const int warp = tid >> 5;
    const int lane = tid & 31;
    const int wm = (warp >> 2) * 64;
    const int wn = (warp & 3) * 32;

    float acc[4][4][4];
    #pragma unroll
    for (int i = 0; i < 4; i++)
        #pragma unroll
        for (int j = 0; j < 4; j++)
            #pragma unroll
            for (int r = 0; r < 4; r++) acc[i][j][r] = 0.f;

    // Prefetch registers: 2 uint4 per array per thread (512 uint4 per tile).
    uint4 rah[2], ral[2], rbh[2], rbl[2];
    const int prow = tid >> 2;          // 0..63? no: idx>>2 over 0..511
    const int pseg = (tid & 3) * 8;

    #pragma unroll
    for (int u = 0; u < 2; u++) {
        const int idx = tid + u * 256;
        const int r = idx >> 2, s = (idx & 3) * 8;
        rah[u] = *(const uint4*)&g_xh[(m0 + r) * E_ + s];
        ral[u] = *(const uint4*)&g_xl[(m0 + r) * E_ + s];
        rbh[u] = *(const uint4*)&Wh[(n0 + r) * E_ + s];
        rbl[u] = *(const uint4*)&Wl[(n0 + r) * E_ + s];
    }
    (void)prow; (void)pseg;

    for (int k0 = 0; k0 < E_; k0 += TBK) {
        #pragma unroll
        for (int u = 0; u < 2; u++) {
            const int idx = tid + u * 256;
            const int r = idx >> 2, s = (idx & 3) * 8;
            *(uint4*)&Ah[r][s] = rah[u];
            *(uint4*)&Al[r][s] = ral[u];
            *(uint4*)&Bh[r][s] = rbh[u];
            *(uint4*)&Bl[r][s] = rbl[u];
        }
        __syncthreads();

        if (k0 + TBK < E_) {
            const int kn = k0 + TBK;
            #pragma unroll
            for (int u = 0; u < 2; u++) {
                const int idx = tid + u * 256;
                const int r = idx >> 2, s = (idx & 3) * 8;
                rah[u] = *(const uint4*)&g_xh[(m0 + r) * E_ + kn + s];
                ral[u] = *(const uint4*)&g_xl[(m0 + r) * E_ + kn + s];
                rbh[u] = *(const uint4*)&Wh[(n0 + r) * E_ + kn + s];
                rbl[u] = *(const uint4*)&Wl[(n0 + r) * E_ + kn + s];
            }
        }

        #pragma unroll
        for (int kk = 0; kk < TBK; kk += 16) {
            uint32_t ah[4][4], al[4][4];
            const int ar = wm + (lane >> 2);
            const int ac = kk + ((lane & 3) << 1);
            #pragma unroll
            for (int im = 0; im < 4; im++) {
                const int r = ar + im * 16;
                ah[im][0] = *(const uint32_t*)&Ah[r    ][ac    ];
                ah[im][1] = *(const uint32_t*)&Ah[r + 8][ac    ];
                ah[im][2] = *(const uint32_t*)&Ah[r    ][ac + 8];
                ah[im][3] = *(const uint32_t*)&Ah[r + 8][ac + 8];
                al[im][0] = *(const uint32_t*)&Al[r    ][ac    ];
                al[im][1] = *(const uint32_t*)&Al[r + 8][ac    ];
                al[im][2] = *(const uint32_t*)&Al[r    ][ac + 8];
                al[im][3] = *(const uint32_t*)&Al[r + 8][ac + 8];
            }
            uint32_t bhf[4][2], blf[4][2];
            const int bn = wn + (lane >> 2);
            const int bc = kk + ((lane & 3) << 1);
            #pragma unroll
            for (int jn = 0; jn < 4; jn++) {
                const int n = bn + jn * 8;
                bhf[jn][0] = *(const uint32_t*)&Bh[n][bc    ];
                bhf[jn][1] = *(const uint32_t*)&Bh[n][bc + 8];
                blf[jn][0] = *(const uint32_t*)&Bl[n][bc    ];
                blf[jn][1] = *(const uint32_t*)&Bl[n][bc + 8];
            }
            #pragma unroll
            for (int im = 0; im < 4; im++)
                #pragma unroll
                for (int jn = 0; jn < 4; jn++) {
                    mma16816(acc[im][jn], ah[im], bhf[jn]);
                    mma16816(acc[im][jn], ah[im], blf[jn]);
                    mma16816(acc[im][jn], al[im], bhf[jn]);
                }
        }
        __syncthreads();
    }

    // ---- epilogue: add bias, split to bf16 hi/lo, write scratch ----
    if (which < 2) {
        __nv_bfloat16* __restrict__ oh = (which == 0) ? g_qh : g_kh;
        __nv_bfloat16* __restrict__ ol = (which == 0) ? g_ql : g_kl;
        #pragma unroll
        for (int jn = 0; jn < 4; jn++) {
            const int ncol = n0 + wn + jn * 8 + ((lane & 3) << 1);
            const int hh = ncol >> 6;
            const int d  = ncol & 63;
            const float b0v = bias[ncol], b1v = bias[ncol + 1];
            #pragma unroll
            for (int im = 0; im < 4; im++) {
                const int row = m0 + wm + im * 16 + (lane >> 2);
                const int bb = row >> 10;
                const int s  = row & (S_ - 1);
                const int base = ((bb * H_ + hh) * S_ + s) * D_ + d;
                __nv_bfloat16 h0, l0, h1, l1;
                split_bf16(acc[im][jn][0] + b0v, h0, l0);
                split_bf16(acc[im][jn][1] + b1v, h1, l1);
                *(uint32_t*)&oh[base] = pack_bf2(h0, h1);
                *(uint32_t*)&ol[base] = pack_bf2(l0, l1);
                split_bf16(acc[im][jn][2] + b0v, h0, l0);
                split_bf16(acc[im][jn][3] + b1v, h1, l1);
                *(uint32_t*)&oh[base + 8 * D_] = pack_bf2(h0, h1);
                *(uint32_t*)&ol[base + 8 * D_] = pack_bf2(l0, l1);
            }
        }
    } else {
        // V: scatter-transpose to [bh][d][s]
        #pragma unroll
        for (int jn = 0; jn < 4; jn++) {
            const int ncol = n0 + wn + jn * 8 + ((lane & 3) << 1);
            const int hh = ncol >> 6;
            const int d  = ncol & 63;
            const float b0v = bias[ncol], b1v = bias[ncol + 1];
            #pragma unroll
            for (int im = 0; im < 4; im++) {
                const int row = m0 + wm + im * 16 + (lane >> 2);
                const int bb = row >> 10;
                const int s  = row & (S_ - 1);
                const int vb = ((bb * H_ + hh) * D_ + d) * S_ + s;
                __nv_bfloat16 h, l;
                split_bf16(acc[im][jn][0] + b0v, h, l);
                g_vth[vb] = h;            g_vtl[vb] = l;
                split_bf16(acc[im][jn][1] + b1v, h, l);
                g_vth[vb + S_] = h;       g_vtl[vb + S_] = l;
                split_bf16(acc[im][jn][2] + b0v, h, l);
                g_vth[vb + 8] = h;        g_vtl[vb + 8] = l;
                split_bf16(acc[im][jn][3] + b1v, h, l);
                g_vth[vb + S_ + 8] = h;   g_vtl[vb + S_ + 8] = l;
            }
        }
    }
}

// ---------------------------------------------------------------------------
// MMA flash attention. 128 threads (4 warps), 64 q rows per block.
// ---------------------------------------------------------------------------
#define ALD 72
#define AT_SMEM_BYTES (6 * 64 * ALD * 2)

__global__ __launch_bounds__(128)
void attn_mma(const int* __restrict__ lens, float* __restrict__ out)
{
    extern __shared__ char smem_raw[];
    __nv_bfloat16* Qh  = (__nv_bfloat16*)smem_raw;
    __nv_bfloat16* Ql  = Qh  + 64 * ALD;
    __nv_bfloat16* Kh  = Ql  + 64 * ALD;
    __nv_bfloat16* Kl  = Kh  + 64 * ALD;
    __nv_bfloat16* Vth = Kl  + 64 * ALD;   // [d][t]
    __nv_bfloat16* Vtl = Vth + 64 * ALD;

    const int bh = blockIdx.y;
    const int b  = bh >> 4;
    const int h  = bh & (H_ - 1);
    const int len = lens[b];
    const int q0 = blockIdx.x * 64;
    const int tid = threadIdx.x;

    // ---- Shortcut: whole block invalid -> uniform mean of V ----
    if (q0 >= len) {
        float* red = (float*)smem_raw;
        const int d = tid & 63;
        const int half = tid >> 6;
        const uint4* ph = (const uint4*)(g_vth + (bh * D_ + d) * S_) + half * 64;
        const uint4* pl = (const uint4*)(g_vtl + (bh * D_ + d) * S_) + half * 64;
        float a = 0.f;
        for (int i = 0; i < 64; i++) {
            uint4 xh = ph[i], xl = pl[i];
            const __nv_bfloat162* eh = (const __nv_bfloat162*)&xh;
            const __nv_bfloat162* el = (const __nv_bfloat162*)&xl;
            #pragma unroll
            for (int e = 0; e < 4; e++) {
                float2 fh = __bfloat1622float2(eh[e]);
                float2 fl = __bfloat1622float2(el[e]);
                a += fh.x + fh.y + fl.x + fl.y;
            }
        }
        red[half * 64 + d] = a;
        __syncthreads();
        const float m = (red[d] + red[64 + d]) * (1.0f / 1024.0f);
        for (int r = half; r < 64; r += 2)
            out[(b * S_ + q0 + r) * E_ + h * D_ + d] = m;
        return;
    }

    const int warp = tid >> 5;
    const int lane = tid & 31;
    const int wm = warp * 16;

    const size_t qoff = (size_t)bh * S_ * D_;

    #pragma unroll
    for (int u = 0; u < 4; u++) {
        const int idx = tid + u * 128;
        const int r = idx >> 3, seg = idx & 7;
        *(uint4*)&Qh[r * ALD + seg * 8] = *(const uint4*)&g_qh[qoff + (q0 + r) * D_ + seg * 8];
        *(uint4*)&Ql[r * ALD + seg * 8] = *(const uint4*)&g_ql[qoff + (q0 + r) * D_ + seg * 8];
    }

    float m0 = -CUDART_INF_F, m1 = -CUDART_INF_F, l0 = 0.f, l1 = 0.f;
    float o[8][4];
    #pragma unroll
    for (int j = 0; j < 8; j++)
        #pragma unroll
        for (int e = 0; e < 4; e++) o[j][e] = 0.f;

    const bool all_valid = (q0 + 64 <= len);
    const int kend = all_valid ? ((len + 63) & ~63) : S_;
    const float scale = 0.125f;

    const int r0g = q0 + wm + (lane >> 2);
    const int r1g = r0g + 8;
    const bool rv0 = r0g < len, rv1 = r1g < len;

    for (int t0 = 0; t0 < kend; t0 += 64) {
        __syncthreads();
        #pragma unroll
        for (int u = 0; u < 4; u++) {
            const int idx = tid + u * 128;
            const int r = idx >> 3, seg = idx & 7;
            *(uint4*)&Kh[r * ALD + seg * 8]  = *(const uint4*)&g_kh[qoff + (t0 + r) * D_ + seg * 8];
            *(uint4*)&Kl[r * ALD + seg * 8]  = *(const uint4*)&g_kl[qoff + (t0 + r) * D_ + seg * 8];
            *(uint4*)&Vth[r * ALD + seg * 8] = *(const uint4*)&g_vth[(size_t)(bh * D_ + r) * S_ + t0 + seg * 8];
            *(uint4*)&Vtl[r * ALD + seg * 8] = *(const uint4*)&g_vtl[(size_t)(bh * D_ + r) * S_ + t0 + seg * 8];
        }
        __syncthreads();

        float sc[8][4];
        #pragma unroll
        for (int j = 0; j < 8; j++)
            #pragma unroll
            for (int e = 0; e < 4; e++) sc[j][e] = 0.f;

        #pragma unroll
        for (int kk = 0; kk < 64; kk += 16) {
            uint32_t ah[4], al[4];
            const int ar = wm + (lane >> 2);
            const int ac = kk + ((lane & 3) << 1);
            ah[0] = *(const uint32_t*)&Qh[ ar      * ALD + ac    ];
            ah[1] = *(const uint32_t*)&Qh[(ar + 8) * ALD + ac    ];
            ah[2] = *(const uint32_t*)&Qh[ ar      * ALD + ac + 8];
            ah[3] = *(const uint32_t*)&Qh[(ar + 8) * ALD + ac + 8];
            al[0] = *(const uint32_t*)&Ql[ ar      * ALD + ac    ];
            al[1] = *(const uint32_t*)&Ql[(ar + 8) * ALD + ac    ];
            al[2] = *(const uint32_t*)&Ql[ ar      * ALD + ac + 8];
            al[3] = *(const uint32_t*)&Ql[(ar + 8) * ALD + ac + 8];
            #pragma unroll
            for (int j = 0; j < 8; j++) {
                const int br = j * 8 + (lane >> 2);
                const int bc = kk + ((lane & 3) << 1);
                uint32_t bhf[2], blf[2];
                bhf[0] = *(const uint32_t*)&Kh[br * ALD + bc    ];
                bhf[1] = *(const uint32_t*)&Kh[br * ALD + bc + 8];
                blf[0] = *(const uint32_t*)&Kl[br * ALD + bc    ];
                blf[1] = *(const uint32_t*)&Kl[br * ALD + bc + 8];
                mma16816(sc[j], ah, bhf);
                mma16816(sc[j], ah, blf);
                mma16816(sc[j], al, bhf);
            }
        }

        #pragma unroll
        for (int j = 0; j < 8; j++) {
            const int c0 = t0 + j * 8 + ((lane & 3) << 1);
            const bool cv0 = c0 < len, cv1 = (c0 + 1) < len;
            sc[j][0] = (rv0 && cv0) ? sc[j][0] * scale : -1e9f;
            sc[j][1] = (rv0 && cv1) ? sc[j][1] * scale : -1e9f;
            sc[j][2] = (rv1 && cv0) ? sc[j][2] * scale : -1e9f;
            sc[j][3] = (rv1 && cv1) ? sc[j][3] * scale : -1e9f;
        }

        float vm0 = -CUDART_INF_F, vm1 = -CUDART_INF_F;
        #pragma unroll
        for (int j = 0; j < 8; j++) {
            vm0 = fmaxf(vm0, fmaxf(sc[j][0], sc[j][1]));
            vm1 = fmaxf(vm1, fmaxf(sc[j][2], sc[j][3]));
        }
        vm0 = fmaxf(vm0, __shfl_xor_sync(0xffffffffu, vm0, 1));
        vm0 = fmaxf(vm0, __shfl_xor_sync(0xffffffffu, vm0, 2));
        vm1 = fmaxf(vm1, __shfl_xor_sync(0xffffffffu, vm1, 1));
        vm1 = fmaxf(vm1, __shfl_xor_sync(0xffffffffu, vm1, 2));
        const float mn0 = fmaxf(m0, vm0);
        const float mn1 = fmaxf(m1, vm1);
        const float al0 = __expf(m0 - mn0);
        const float al1 = __expf(m1 - mn1);
        m0 = mn0; m1 = mn1;

        float s0 = 0.f, s1 = 0.f;
        #pragma unroll
        for (int j = 0; j < 8; j++) {
            sc[j][0] = __expf(sc[j][0] - mn0); s0 += sc[j][0];
            sc[j][1] = __expf(sc[j][1] - mn0); s0 += sc[j][1];
            sc[j][2] = __expf(sc[j][2] - mn1); s1 += sc[j][2];
            sc[j][3] = __expf(sc[j][3] - mn1); s1 += sc[j][3];
        }
        s0 += __shfl_xor_sync(0xffffffffu, s0, 1);
        s0 += __shfl_xor_sync(0xffffffffu, s0, 2);
        s1 += __shfl_xor_sync(0xffffffffu, s1, 1);
        s1 += __shfl_xor_sync(0xffffffffu, s1, 2);
        l0 = l0 * al0 + s0;
        l1 = l1 * al1 + s1;
        #pragma unroll
        for (int j = 0; j < 8; j++) {
            o[j][0] *= al0; o[j][1] *= al0;
            o[j][2] *= al1; o[j][3] *= al1;
        }

        #pragma unroll
        for (int kp = 0; kp < 4; kp++) {
            const int j0 = kp * 2, j1 = kp * 2 + 1;
            uint32_t pah[4], pal[4];
            {
                __nv_bfloat16 hx, lx, hy, ly;
                split_bf16(sc[j0][0], hx, lx); split_bf16(sc[j0][1], hy, ly);
                pah[0] = pack_bf2(hx, hy); pal[0] = pack_bf2(lx, ly);
                split_bf16(sc[j0][2], hx, lx); split_bf16(sc[j0][3], hy, ly);
                pah[1] = pack_bf2(hx, hy); pal[1] = pack_bf2(lx, ly);
                split_bf16(sc[j1][0], hx, lx); split_bf16(sc[j1][1], hy, ly);
                pah[2] = pack_bf2(hx, hy); pal[2] = pack_bf2(lx, ly);
                split_bf16(sc[j1][2], hx, lx); split_bf16(sc[j1][3], hy, ly);
                pah[3] = pack_bf2(hx, hy); pal[3] = pack_bf2(lx, ly);
            }
            #pragma unroll
            for (int j = 0; j < 8; j++) {
                const int br = j * 8 + (lane >> 2);
                const int bc = kp * 16 + ((lane & 3) << 1);
                uint32_t bhf[2], blf[2];
                bhf[0] = *(const uint32_t*)&Vth[br * ALD + bc    ];
                bhf[1] = *(const uint32_t*)&Vth[br * ALD + bc + 8];
                blf[0] = *(const uint32_t*)&Vtl[br * ALD + bc    ];
                blf[1] = *(const uint32_t*)&Vtl[br * ALD + bc + 8];
                mma16816(o[j], pah, bhf);
                mma16816(o[j], pah, blf);
                mma16816(o[j], pal, bhf);
            }
        }
    }

    const float inv0 = 1.f / l0;
    const float inv1 = 1.f / l1;
    #pragma unroll
    for (int j = 0; j < 8; j++) {
        const int d = j * 8 + ((lane & 3) << 1);
        float2 w0 = make_float2(o[j][0] * inv0, o[j][1] * inv0);
        float2 w1 = make_float2(o[j][2] * inv1, o[j][3] * inv1);
        *(float2*)&out[(b * S_ + r0g) * E_ + h * D_ + d] = w0;
        *(float2*)&out[(b * S_ + r1g) * E_ + h * D_ + d] = w1;
    }
}

// ---------------------------------------------------------------------------
extern "C" void kernel_launch(void* const* d_in, const int* in_sizes, int n_in,
                              void* d_out, int out_size)
{
    const float* x   = (const float*)d_in[0];
    const float* Wq  = (const float*)d_in[1];
    const float* bq  = (const float*)d_in[2];
    const float* Wk  = (const float*)d_in[3];
    const float* bk  = (const float*)d_in[4];
    const float* Wv  = (const float*)d_in[5];
    const float* bv  = (const float*)d_in[6];
    const int*  lens = (const int*)d_in[7];
    float* out = (float*)d_out;

    // Pre-split passes
    xsplit<<<M_ * E_ / (256 * 8), 256>>>(x);
    dim3 wgrid(E_ / 32, E_ / 32, 3);
    wsplit<<<wgrid, dim3(32, 8)>>>(Wq, Wk, Wv);

    // Projections
    dim3 ggrid(E_ / TBN, M_ / TBM, 3);
    qkv_mma<<<ggrid, 256>>>(bq, bk, bv);

    // Attention
    cudaFuncSetAttribute(attn_mma,
                         cudaFuncAttributeMaxDynamicSharedMemorySize, AT_SMEM_BYTES);
    dim3 agrid(S_ / 64, B_ * H_);
    attn_mma<<<agrid, 128, AT_SMEM_BYTES>>>(lens, out);
}